// round 2
// baseline (speedup 1.0000x reference)
#include <cuda_runtime.h>

#define BATCH 256
#define SEQ   64
#define DIMW  1024
#define SDIMW 256
#define MROWS (BATCH*SEQ)   // 16384
#define EPS   1e-5f

// ---------------- scratch (static device globals; no runtime allocation) ----
__device__ float g_decay[MROWS * SDIMW];          // 16.8 MB
__device__ float g_drive[MROWS * SDIMW];          // 16.8 MB
__device__ float g_hs   [MROWS * SDIMW];          // 16.8 MB
__device__ float g_hidden[(size_t)MROWS * DIMW];  // 64 MB (layer-0 output)
__device__ float g_final [BATCH * SDIMW];
__device__ float g_cstate[BATCH * DIMW];

__device__ __forceinline__ float softplusf(float x) {
    // stable: max(x,0) + log(1 + exp(-|x|)); fast intrinsics OK (abs err ~1e-6)
    float e = __expf(-fabsf(x));
    return fmaxf(x, 0.f) + __logf(1.f + e);
}

// ---------------------------------------------------------------------------
// Kernel 1: fused input projections + gate elementwise.
//   X:[M,1024]  Wd,Wi:[1024,256]  ->  decay,drive:[M,256]
// Tiles: BM=64, BN=64, BK=16; 256 threads; 4x4 microtile; dual accumulators.
// ---------------------------------------------------------------------------
__global__ __launch_bounds__(256)
void proj_kernel(const float* __restrict__ X,
                 const float* __restrict__ Wd, const float* __restrict__ Wi,
                 const float* __restrict__ bd, const float* __restrict__ bi,
                 const float* __restrict__ A_log,
                 float* __restrict__ decay, float* __restrict__ drive)
{
    __shared__ float Xs[16][68];     // k-major, padded
    __shared__ float Bd[16][64];
    __shared__ float Bi[16][64];
    __shared__ float spA[64];

    const int tid = threadIdx.x;
    const int m0 = blockIdx.y * 64;
    const int n0 = blockIdx.x * 64;

    if (tid < 64) spA[tid] = softplusf(A_log[n0 + tid]);

    const int lr = tid >> 2;     // X row within tile (0..63)
    const int lc = tid & 3;      // which float4 of the 16-wide k slab
    const int wr = tid >> 4;     // W k-row (0..15)
    const int wc = tid & 15;     // which float4 of the 64-wide n slab
    const int ty = tid >> 4;     // microtile row group (0..15)
    const int tx = tid & 15;     // microtile col group (0..15)

    float accd[4][4] = {};
    float acci[4][4] = {};

    for (int k0 = 0; k0 < DIMW; k0 += 16) {
        float4 xv = *(const float4*)(X  + (size_t)(m0 + lr) * DIMW  + k0 + lc * 4);
        float4 dv = *(const float4*)(Wd + (size_t)(k0 + wr) * SDIMW + n0 + wc * 4);
        float4 iv = *(const float4*)(Wi + (size_t)(k0 + wr) * SDIMW + n0 + wc * 4);
        __syncthreads();
        Xs[lc * 4 + 0][lr] = xv.x;
        Xs[lc * 4 + 1][lr] = xv.y;
        Xs[lc * 4 + 2][lr] = xv.z;
        Xs[lc * 4 + 3][lr] = xv.w;
        *(float4*)&Bd[wr][wc * 4] = dv;
        *(float4*)&Bi[wr][wc * 4] = iv;
        __syncthreads();
        #pragma unroll
        for (int kk = 0; kk < 16; kk++) {
            float4 a  = *(const float4*)&Xs[kk][ty * 4];
            float4 b1 = *(const float4*)&Bd[kk][tx * 4];
            float4 b2 = *(const float4*)&Bi[kk][tx * 4];
            float av[4] = {a.x, a.y, a.z, a.w};
            float d1[4] = {b1.x, b1.y, b1.z, b1.w};
            float d2[4] = {b2.x, b2.y, b2.z, b2.w};
            #pragma unroll
            for (int i = 0; i < 4; i++)
                #pragma unroll
                for (int j = 0; j < 4; j++) {
                    accd[i][j] = fmaf(av[i], d1[j], accd[i][j]);
                    acci[i][j] = fmaf(av[i], d2[j], acci[i][j]);
                }
        }
    }

    #pragma unroll
    for (int i = 0; i < 4; i++) {
        const int m = m0 + ty * 4 + i;
        #pragma unroll
        for (int j = 0; j < 4; j++) {
            const int n = n0 + tx * 4 + j;
            float dr = accd[i][j] + bd[n];
            float ur = acci[i][j] + bi[n];
            float delta = softplusf(dr);
            float dec = __expf(-delta * spA[tx * 4 + j]);
            size_t idx = (size_t)m * SDIMW + n;
            decay[idx] = dec;
            drive[idx] = delta * ur;
        }
    }
}

// ---------------------------------------------------------------------------
// Kernel 2: selective scan over S. thread = (b, n). Coalesced over n.
// ---------------------------------------------------------------------------
__global__ __launch_bounds__(256)
void scan_kernel(const float* __restrict__ decay, const float* __restrict__ drive,
                 float* __restrict__ hs, float* __restrict__ fin)
{
    const int b = blockIdx.x;
    const int n = threadIdx.x;
    size_t base = (size_t)b * SEQ * SDIMW + n;
    float h = 0.f;
    #pragma unroll 8
    for (int s = 0; s < SEQ; s++) {
        size_t idx = base + (size_t)s * SDIMW;
        h = fmaf(decay[idx], h, drive[idx]);
        hs[idx] = h;
    }
    fin[b * SDIMW + n] = h;
}

// ---------------------------------------------------------------------------
// Kernel 3: class_state = final @ Ws + bs   ([256,256] x [256,1024])
// block = (d-chunk of 256, b); smem broadcast of final[b,:]
// ---------------------------------------------------------------------------
__global__ __launch_bounds__(256)
void cstate_kernel(const float* __restrict__ fin, const float* __restrict__ Ws,
                   const float* __restrict__ bs, float* __restrict__ cs)
{
    __shared__ float sf[SDIMW];
    const int b = blockIdx.y;
    const int d = blockIdx.x * 256 + threadIdx.x;
    sf[threadIdx.x] = fin[b * SDIMW + threadIdx.x];
    __syncthreads();
    float acc = bs[d];
    #pragma unroll 8
    for (int n = 0; n < SDIMW; n++)
        acc = fmaf(sf[n], Ws[(size_t)n * DIMW + d], acc);
    cs[(size_t)b * DIMW + d] = acc;
}

// ---------------------------------------------------------------------------
// Kernel 4: Y = hs @ Wo + bo + cstate[b]   ([M,256] x [256,1024])
// BM=64 == SEQ, so one block row == one batch element (b = blockIdx.y).
// ---------------------------------------------------------------------------
__global__ __launch_bounds__(256)
void outgemm_kernel(const float* __restrict__ HS, const float* __restrict__ Wo,
                    const float* __restrict__ bo, const float* __restrict__ cs,
                    float* __restrict__ out)
{
    __shared__ float As[16][68];
    __shared__ float Bs[16][64];

    const int tid = threadIdx.x;
    const int m0 = blockIdx.y * 64;
    const int n0 = blockIdx.x * 64;
    const int bidx = blockIdx.y;   // batch element (SEQ == BM == 64)

    const int lr = tid >> 2;
    const int lc = tid & 3;
    const int wr = tid >> 4;
    const int wc = tid & 15;
    const int ty = tid >> 4;
    const int tx = tid & 15;

    float acc[4][4] = {};

    for (int k0 = 0; k0 < SDIMW; k0 += 16) {
        float4 av = *(const float4*)(HS + (size_t)(m0 + lr) * SDIMW + k0 + lc * 4);
        float4 bv = *(const float4*)(Wo + (size_t)(k0 + wr) * DIMW  + n0 + wc * 4);
        __syncthreads();
        As[lc * 4 + 0][lr] = av.x;
        As[lc * 4 + 1][lr] = av.y;
        As[lc * 4 + 2][lr] = av.z;
        As[lc * 4 + 3][lr] = av.w;
        *(float4*)&Bs[wr][wc * 4] = bv;
        __syncthreads();
        #pragma unroll
        for (int kk = 0; kk < 16; kk++) {
            float4 a = *(const float4*)&As[kk][ty * 4];
            float4 b = *(const float4*)&Bs[kk][tx * 4];
            float avv[4] = {a.x, a.y, a.z, a.w};
            float bvv[4] = {b.x, b.y, b.z, b.w};
            #pragma unroll
            for (int i = 0; i < 4; i++)
                #pragma unroll
                for (int j = 0; j < 4; j++)
                    acc[i][j] = fmaf(avv[i], bvv[j], acc[i][j]);
        }
    }

    #pragma unroll
    for (int i = 0; i < 4; i++) {
        const int m = m0 + ty * 4 + i;
        #pragma unroll
        for (int j = 0; j < 4; j++) {
            const int n = n0 + tx * 4 + j;
            out[(size_t)m * DIMW + n] =
                acc[i][j] + bo[n] + cs[(size_t)bidx * DIMW + n];
        }
    }
}

// ---------------------------------------------------------------------------
// Kernel 5: pooled = cstate + mean_s(hidden); LayerNorm -> class_repr
// one block per b; 256 threads; 4 d's per thread.
// ---------------------------------------------------------------------------
__global__ __launch_bounds__(256)
void final_kernel(const float* __restrict__ hid, const float* __restrict__ cs,
                  const float* __restrict__ gamma, const float* __restrict__ beta,
                  float* __restrict__ out)
{
    const int b = blockIdx.x;
    const int tid = threadIdx.x;

    float pooled[4];
    float lsum = 0.f, lsq = 0.f;
    #pragma unroll
    for (int i = 0; i < 4; i++) {
        const int d = i * 256 + tid;
        float acc = 0.f;
        #pragma unroll 8
        for (int s = 0; s < SEQ; s++)
            acc += hid[((size_t)b * SEQ + s) * DIMW + d];
        float p = cs[(size_t)b * DIMW + d] + acc * (1.f / (float)SEQ);
        pooled[i] = p;
        lsum += p;
        lsq  += p * p;
    }

    __shared__ float s1[8], s2[8];
    #pragma unroll
    for (int o = 16; o > 0; o >>= 1) {
        lsum += __shfl_xor_sync(0xffffffffu, lsum, o);
        lsq  += __shfl_xor_sync(0xffffffffu, lsq,  o);
    }
    if ((tid & 31) == 0) { s1[tid >> 5] = lsum; s2[tid >> 5] = lsq; }
    __syncthreads();
    float tsum = 0.f, tsq = 0.f;
    #pragma unroll
    for (int w = 0; w < 8; w++) { tsum += s1[w]; tsq += s2[w]; }

    const float mu  = tsum * (1.f / (float)DIMW);
    const float var = tsq * (1.f / (float)DIMW) - mu * mu;
    const float rstd = rsqrtf(var + EPS);

    #pragma unroll
    for (int i = 0; i < 4; i++) {
        const int d = i * 256 + tid;
        out[(size_t)b * DIMW + d] = (pooled[i] - mu) * rstd * gamma[d] + beta[d];
    }
}

// ---------------------------------------------------------------------------
extern "C" void kernel_launch(void* const* d_in, const int* in_sizes, int n_in,
                              void* d_out, int out_size)
{
    const float* X     = (const float*)d_in[0];
    const float* Wd    = (const float*)d_in[1];
    const float* bd    = (const float*)d_in[2];
    const float* Wi    = (const float*)d_in[3];
    const float* bi    = (const float*)d_in[4];
    const float* A_log = (const float*)d_in[5];
    const float* Wo    = (const float*)d_in[6];
    const float* bo    = (const float*)d_in[7];
    const float* Ws    = (const float*)d_in[8];
    const float* bs    = (const float*)d_in[9];
    const float* gamma = (const float*)d_in[10];
    const float* beta  = (const float*)d_in[11];

    float* out_repr   = (float*)d_out;                         // [B, D]
    float* out_hidden = (float*)d_out + (size_t)BATCH * DIMW;  // [B, S, D]

    float *p_decay, *p_drive, *p_hs, *p_hidden, *p_final, *p_cstate;
    cudaGetSymbolAddress((void**)&p_decay,  g_decay);
    cudaGetSymbolAddress((void**)&p_drive,  g_drive);
    cudaGetSymbolAddress((void**)&p_hs,     g_hs);
    cudaGetSymbolAddress((void**)&p_hidden, g_hidden);
    cudaGetSymbolAddress((void**)&p_final,  g_final);
    cudaGetSymbolAddress((void**)&p_cstate, g_cstate);

    const dim3 projGrid(SDIMW / 64, MROWS / 64);   // (4, 256)
    const dim3 outGrid (DIMW  / 64, MROWS / 64);   // (16, 256)
    const dim3 csGrid  (DIMW / 256, BATCH);        // (4, 256)

    const size_t DN = (size_t)DIMW * SDIMW;  // per-layer weight stride (Wd/Wi)
    const size_t ND = (size_t)SDIMW * DIMW;  // per-layer weight stride (Wo/Ws)

    // ---------------- layer 0 ----------------
    proj_kernel<<<projGrid, 256>>>(X, Wd, Wi, bd, bi, A_log, p_decay, p_drive);
    scan_kernel<<<BATCH, 256>>>(p_decay, p_drive, p_hs, p_final);
    cstate_kernel<<<csGrid, 256>>>(p_final, Ws, bs, p_cstate);
    outgemm_kernel<<<outGrid, 256>>>(p_hs, Wo, bo, p_cstate, p_hidden);

    // ---------------- layer 1 ----------------
    proj_kernel<<<projGrid, 256>>>(p_hidden, Wd + DN, Wi + DN, bd + SDIMW,
                                   bi + SDIMW, A_log + SDIMW, p_decay, p_drive);
    scan_kernel<<<BATCH, 256>>>(p_decay, p_drive, p_hs, p_final);
    cstate_kernel<<<csGrid, 256>>>(p_final, Ws + ND, bs + DIMW, p_cstate);
    outgemm_kernel<<<outGrid, 256>>>(p_hs, Wo + ND, bo + DIMW, p_cstate, out_hidden);

    // ---------------- pooling + LayerNorm ----------------
    final_kernel<<<BATCH, 256>>>(out_hidden, p_cstate, gamma, beta, out_repr);
}

// round 5
// speedup vs baseline: 2.6469x; 2.6469x over previous
#include <cuda_runtime.h>
#include <cstdint>

#define BATCH 256
#define SEQ   64
#define DIMW  1024
#define SDIMW 256
#define MROWS (BATCH*SEQ)   // 16384
#define EPS   1e-5f

// ---------------- scratch (static device globals; no runtime allocation) ----
__device__ float g_decay[MROWS * SDIMW];
__device__ float g_drive[MROWS * SDIMW];
__device__ float g_hs   [MROWS * SDIMW];
__device__ float g_hidden[(size_t)MROWS * DIMW];
__device__ float g_final [BATCH * SDIMW];
__device__ float g_cstate[BATCH * DIMW];
__device__ float g_wt[6 * SDIMW * DIMW];   // transposed + tf32-rounded weights

__device__ __forceinline__ float softplusf(float x) {
    float e = __expf(-fabsf(x));
    return fmaxf(x, 0.f) + __logf(1.f + e);
}
__device__ __forceinline__ float tf32r(float f) {
    uint32_t r;
    asm("cvt.rna.tf32.f32 %0, %1;" : "=r"(r) : "f"(f));
    return __uint_as_float(r);
}
__device__ __forceinline__ float4 tf32r4(float4 v) {
    return make_float4(tf32r(v.x), tf32r(v.y), tf32r(v.z), tf32r(v.w));
}
__device__ __forceinline__ uint32_t smem_u32(const void* p) {
    uint32_t a;
    asm("{ .reg .u64 t; cvta.to.shared.u64 t, %1; cvt.u32.u64 %0, t; }"
        : "=r"(a) : "l"(p));
    return a;
}
__device__ __forceinline__ void ldm_x4(uint32_t addr, uint32_t* r) {
    asm volatile("ldmatrix.sync.aligned.m8n8.x4.shared.b16 {%0,%1,%2,%3}, [%4];"
                 : "=r"(r[0]), "=r"(r[1]), "=r"(r[2]), "=r"(r[3]) : "r"(addr));
}
__device__ __forceinline__ void mma8(float* c, const uint32_t* a, const uint32_t* b) {
    asm volatile("mma.sync.aligned.m16n8k8.row.col.f32.tf32.tf32.f32 "
                 "{%0,%1,%2,%3}, {%4,%5,%6,%7}, {%8,%9}, {%0,%1,%2,%3};"
                 : "+f"(c[0]), "+f"(c[1]), "+f"(c[2]), "+f"(c[3])
                 : "r"(a[0]), "r"(a[1]), "r"(a[2]), "r"(a[3]),
                   "r"(b[0]), "r"(b[1]));
}

// ---------------------------------------------------------------------------
// Transpose + tf32-round: src[R,C] -> dst[C,R]
// ---------------------------------------------------------------------------
__global__ void transpose_kernel(const float* __restrict__ src,
                                 float* __restrict__ dst, int R, int C) {
    __shared__ float t[32][33];
    const int c0 = blockIdx.x * 32, r0 = blockIdx.y * 32;
    const int tx = threadIdx.x, ty = threadIdx.y;
    #pragma unroll
    for (int k = 0; k < 4; k++)
        t[ty + 8 * k][tx] = src[(size_t)(r0 + ty + 8 * k) * C + c0 + tx];
    __syncthreads();
    #pragma unroll
    for (int k = 0; k < 4; k++)
        dst[(size_t)(c0 + ty + 8 * k) * R + r0 + tx] = tf32r(t[tx][ty + 8 * k]);
}

// ---------------------------------------------------------------------------
// proj (mma.sync tf32): decay/drive[M,256] from X[M,1024] x {WdT,WiT}[256,1024]
// CTA: 128m x 64n(dual). 8 warps as 4(m) x 2(n), warp tile 32x32. BK=32.
// smem: A 2x16KB @0, Bd 2x8KB @32768, Bi 2x8KB @49152, biases @65536.
// ---------------------------------------------------------------------------
#define PJ_SMEM (65536 + 3 * 64 * 4)
__global__ __launch_bounds__(256)
void proj_mma_kernel(const float* __restrict__ X,
                     const float* __restrict__ WdT, const float* __restrict__ WiT,
                     const float* __restrict__ bd, const float* __restrict__ bi,
                     const float* __restrict__ A_log,
                     float* __restrict__ decay, float* __restrict__ drive)
{
    extern __shared__ char smem[];
    const uint32_t sbase = smem_u32(smem);
    const int tid = threadIdx.x, wid = tid >> 5, lane = tid & 31;
    const int wm = wid & 3, wn = wid >> 2;
    const int m0 = blockIdx.y * 128, n0 = blockIdx.x * 64;

    float* sbd = (float*)(smem + 65536);
    float* sbi = sbd + 64;
    float* ssa = sbi + 64;
    if (tid < 64) {
        sbd[tid] = bd[n0 + tid];
        sbi[tid] = bi[n0 + tid];
        ssa[tid] = softplusf(A_log[n0 + tid]);
    }

    // per-thread loader coords
    const int lrow4 = tid >> 3, lc16 = tid & 7;     // A/B slot for i-th chunk
    // per-thread ldmatrix coords
    const int swz = lane & 7, sel = lane >> 3;
    const int selr = (sel & 1) * 8, selc = sel >> 1;

    uint32_t aRow[2], bRow[4];
    #pragma unroll
    for (int mt = 0; mt < 2; mt++)
        aRow[mt] = (uint32_t)((wm * 32 + mt * 16 + selr + swz) * 128);
    #pragma unroll
    for (int nt = 0; nt < 4; nt++)
        bRow[nt] = (uint32_t)((wn * 32 + nt * 8 + swz) * 128);

    float accD[2][4][4] = {};
    float accI[2][4][4] = {};

    float4 aS[4], dS[2], iS[2];

    // ---- prologue load kt=0 ----
    {
        const int k0 = 0;
        #pragma unroll
        for (int i = 0; i < 4; i++) {
            const int row = lrow4 + i * 32;
            aS[i] = *(const float4*)(X + (size_t)(m0 + row) * DIMW + k0 + lc16 * 4);
        }
        #pragma unroll
        for (int i = 0; i < 2; i++) {
            const int row = lrow4 + i * 32;
            dS[i] = *(const float4*)(WdT + (size_t)(n0 + row) * DIMW + k0 + lc16 * 4);
            iS[i] = *(const float4*)(WiT + (size_t)(n0 + row) * DIMW + k0 + lc16 * 4);
        }
        #pragma unroll
        for (int i = 0; i < 4; i++) {
            const int row = lrow4 + i * 32;
            *(float4*)(smem + row * 128 + ((lc16 ^ (row & 7)) << 4)) = tf32r4(aS[i]);
        }
        #pragma unroll
        for (int i = 0; i < 2; i++) {
            const int row = lrow4 + i * 32;
            const uint32_t off = row * 128 + ((lc16 ^ (row & 7)) << 4);
            *(float4*)(smem + 32768 + off) = dS[i];
            *(float4*)(smem + 49152 + off) = iS[i];
        }
    }
    __syncthreads();

    const int KT = DIMW / 32;   // 32
    for (int kt = 0; kt < KT; kt++) {
        const int buf = kt & 1;
        if (kt + 1 < KT) {
            const int k0 = (kt + 1) * 32;
            #pragma unroll
            for (int i = 0; i < 4; i++) {
                const int row = lrow4 + i * 32;
                aS[i] = *(const float4*)(X + (size_t)(m0 + row) * DIMW + k0 + lc16 * 4);
            }
            #pragma unroll
            for (int i = 0; i < 2; i++) {
                const int row = lrow4 + i * 32;
                dS[i] = *(const float4*)(WdT + (size_t)(n0 + row) * DIMW + k0 + lc16 * 4);
                iS[i] = *(const float4*)(WiT + (size_t)(n0 + row) * DIMW + k0 + lc16 * 4);
            }
        }

        // ---- compute on buf ----
        const uint32_t Asm = sbase + buf * 16384;
        const uint32_t Bdsm = sbase + 32768 + buf * 8192;
        const uint32_t Bism = sbase + 49152 + buf * 8192;

        uint32_t af[2][4][4];
        #pragma unroll
        for (int mt = 0; mt < 2; mt++)
            #pragma unroll
            for (int kk = 0; kk < 4; kk++)
                ldm_x4(Asm + aRow[mt] + (((kk * 2 + selc) ^ swz) << 4), af[mt][kk]);

        #pragma unroll
        for (int out = 0; out < 2; out++) {
            const uint32_t Bsm = out ? Bism : Bdsm;
            #pragma unroll
            for (int kh = 0; kh < 2; kh++) {
                uint32_t bf[4][4];
                #pragma unroll
                for (int nt = 0; nt < 4; nt++)
                    ldm_x4(Bsm + bRow[nt] + (((kh * 4 + sel) ^ swz) << 4), bf[nt]);
                #pragma unroll
                for (int kk2 = 0; kk2 < 2; kk2++)
                    #pragma unroll
                    for (int mt = 0; mt < 2; mt++)
                        #pragma unroll
                        for (int nt = 0; nt < 4; nt++)
                            mma8(out ? accI[mt][nt] : accD[mt][nt],
                                 af[mt][kh * 2 + kk2], &bf[nt][kk2 * 2]);
            }
        }

        if (kt + 1 < KT) {
            const int nbuf = (kt + 1) & 1;
            #pragma unroll
            for (int i = 0; i < 4; i++) {
                const int row = lrow4 + i * 32;
                *(float4*)(smem + nbuf * 16384 + row * 128 +
                           ((lc16 ^ (row & 7)) << 4)) = tf32r4(aS[i]);
            }
            #pragma unroll
            for (int i = 0; i < 2; i++) {
                const int row = lrow4 + i * 32;
                const uint32_t off = row * 128 + ((lc16 ^ (row & 7)) << 4);
                *(float4*)(smem + 32768 + nbuf * 8192 + off) = dS[i];
                *(float4*)(smem + 49152 + nbuf * 8192 + off) = iS[i];
            }
        }
        __syncthreads();
    }

    // ---- epilogue ----
    const int g = lane >> 2, t = lane & 3;
    #pragma unroll
    for (int mt = 0; mt < 2; mt++) {
        const int row0 = m0 + wm * 32 + mt * 16 + g;
        #pragma unroll
        for (int nt = 0; nt < 4; nt++) {
            const int nl = wn * 32 + nt * 8 + 2 * t;
            const float b0 = sbd[nl], b1 = sbd[nl + 1];
            const float i0 = sbi[nl], i1 = sbi[nl + 1];
            const float a0 = ssa[nl], a1 = ssa[nl + 1];
            #pragma unroll
            for (int rh = 0; rh < 2; rh++) {
                const int row = row0 + rh * 8;
                const float cd0 = accD[mt][nt][rh * 2 + 0];
                const float cd1 = accD[mt][nt][rh * 2 + 1];
                const float ci0 = accI[mt][nt][rh * 2 + 0];
                const float ci1 = accI[mt][nt][rh * 2 + 1];
                const float de0 = softplusf(cd0 + b0);
                const float de1 = softplusf(cd1 + b1);
                float2 dec = make_float2(__expf(-de0 * a0), __expf(-de1 * a1));
                float2 drv = make_float2(de0 * (ci0 + i0), de1 * (ci1 + i1));
                *(float2*)(decay + (size_t)row * SDIMW + n0 + nl) = dec;
                *(float2*)(drive + (size_t)row * SDIMW + n0 + nl) = drv;
            }
        }
    }
}

// ---------------------------------------------------------------------------
// outgemm (mma.sync tf32): out[M,1024] = hs[M,256] x WoT[1024,256]^T + bo + cs
// CTA: 128m x 128n. 8 warps as 2(m) x 4(n), warp tile 64x32. BK=32.
// smem: A 2x16KB @0, B 2x16KB @32768, bo @65536.
// ---------------------------------------------------------------------------
#define OG_SMEM (65536 + 128 * 4)
__global__ __launch_bounds__(256)
void outgemm_mma_kernel(const float* __restrict__ HS, const float* __restrict__ WoT,
                        const float* __restrict__ bo, const float* __restrict__ cs,
                        float* __restrict__ out)
{
    extern __shared__ char smem[];
    const uint32_t sbase = smem_u32(smem);
    const int tid = threadIdx.x, wid = tid >> 5, lane = tid & 31;
    const int wm = wid & 1, wn = wid >> 1;
    const int m0 = blockIdx.y * 128, n0 = blockIdx.x * 128;

    float* sbo = (float*)(smem + 65536);
    if (tid < 128) sbo[tid] = bo[n0 + tid];

    const int lrow4 = tid >> 3, lc16 = tid & 7;
    const int swz = lane & 7, sel = lane >> 3;
    const int selr = (sel & 1) * 8, selc = sel >> 1;

    uint32_t aRow[4], bRow[4];
    #pragma unroll
    for (int mt = 0; mt < 4; mt++)
        aRow[mt] = (uint32_t)((wm * 64 + mt * 16 + selr + swz) * 128);
    #pragma unroll
    for (int nt = 0; nt < 4; nt++)
        bRow[nt] = (uint32_t)((wn * 32 + nt * 8 + swz) * 128);

    float acc[4][4][4] = {};
    float4 aS[4], bS[4];

    {
        #pragma unroll
        for (int i = 0; i < 4; i++) {
            const int row = lrow4 + i * 32;
            aS[i] = *(const float4*)(HS  + (size_t)(m0 + row) * SDIMW + lc16 * 4);
            bS[i] = *(const float4*)(WoT + (size_t)(n0 + row) * SDIMW + lc16 * 4);
        }
        #pragma unroll
        for (int i = 0; i < 4; i++) {
            const int row = lrow4 + i * 32;
            const uint32_t off = row * 128 + ((lc16 ^ (row & 7)) << 4);
            *(float4*)(smem + off) = aS[i];
            *(float4*)(smem + 32768 + off) = bS[i];
        }
    }
    __syncthreads();

    const int KT = SDIMW / 32;   // 8
    for (int kt = 0; kt < KT; kt++) {
        const int buf = kt & 1;
        if (kt + 1 < KT) {
            const int k0 = (kt + 1) * 32;
            #pragma unroll
            for (int i = 0; i < 4; i++) {
                const int row = lrow4 + i * 32;
                aS[i] = *(const float4*)(HS  + (size_t)(m0 + row) * SDIMW + k0 + lc16 * 4);
                bS[i] = *(const float4*)(WoT + (size_t)(n0 + row) * SDIMW + k0 + lc16 * 4);
            }
        }

        const uint32_t Asm = sbase + buf * 16384;
        const uint32_t Bsm = sbase + 32768 + buf * 16384;

        #pragma unroll
        for (int kh = 0; kh < 2; kh++) {
            uint32_t bf[4][4];
            #pragma unroll
            for (int nt = 0; nt < 4; nt++)
                ldm_x4(Bsm + bRow[nt] + (((kh * 4 + sel) ^ swz) << 4), bf[nt]);
            #pragma unroll
            for (int kk2 = 0; kk2 < 2; kk2++) {
                const int kk = kh * 2 + kk2;
                uint32_t af[4][4];
                #pragma unroll
                for (int mt = 0; mt < 4; mt++)
                    ldm_x4(Asm + aRow[mt] + (((kk * 2 + selc) ^ swz) << 4), af[mt]);
                #pragma unroll
                for (int mt = 0; mt < 4; mt++)
                    #pragma unroll
                    for (int nt = 0; nt < 4; nt++)
                        mma8(acc[mt][nt], af[mt], &bf[nt][kk2 * 2]);
            }
        }

        if (kt + 1 < KT) {
            const int nbuf = (kt + 1) & 1;
            #pragma unroll
            for (int i = 0; i < 4; i++) {
                const int row = lrow4 + i * 32;
                const uint32_t off = row * 128 + ((lc16 ^ (row & 7)) << 4);
                *(float4*)(smem + nbuf * 16384 + off) = aS[i];
                *(float4*)(smem + 32768 + nbuf * 16384 + off) = bS[i];
            }
        }
        __syncthreads();
    }

    // epilogue: b (batch) constant per (CTA, wm) since warp m-span = 64 == SEQ
    const int g = lane >> 2, t = lane & 3;
    const int bb = blockIdx.y * 2 + wm;
    #pragma unroll
    for (int nt = 0; nt < 4; nt++) {
        const int nl = wn * 32 + nt * 8 + 2 * t;
        const float2 cv = *(const float2*)(cs + (size_t)bb * DIMW + n0 + nl);
        const float add0 = sbo[nl] + cv.x;
        const float add1 = sbo[nl + 1] + cv.y;
        #pragma unroll
        for (int mt = 0; mt < 4; mt++) {
            const int row0 = m0 + wm * 64 + mt * 16 + g;
            #pragma unroll
            for (int rh = 0; rh < 2; rh++) {
                const int row = row0 + rh * 8;
                float2 ov = make_float2(acc[mt][nt][rh * 2 + 0] + add0,
                                        acc[mt][nt][rh * 2 + 1] + add1);
                *(float2*)(out + (size_t)row * DIMW + n0 + nl) = ov;
            }
        }
    }
}

// ---------------------------------------------------------------------------
// scan: thread = (b, n). hs written tf32-rounded (feeds only the outgemm).
// ---------------------------------------------------------------------------
__global__ __launch_bounds__(256)
void scan_kernel(const float* __restrict__ decay, const float* __restrict__ drive,
                 float* __restrict__ hs, float* __restrict__ fin)
{
    const int b = blockIdx.x;
    const int n = threadIdx.x;
    size_t base = (size_t)b * SEQ * SDIMW + n;
    float h = 0.f;
    #pragma unroll 8
    for (int s = 0; s < SEQ; s++) {
        size_t idx = base + (size_t)s * SDIMW;
        h = fmaf(decay[idx], h, drive[idx]);
        hs[idx] = tf32r(h);
    }
    fin[b * SDIMW + n] = h;
}

__global__ __launch_bounds__(256)
void cstate_kernel(const float* __restrict__ fin, const float* __restrict__ Ws,
                   const float* __restrict__ bs, float* __restrict__ cs)
{
    __shared__ float sf[SDIMW];
    const int b = blockIdx.y;
    const int d = blockIdx.x * 256 + threadIdx.x;
    sf[threadIdx.x] = fin[b * SDIMW + threadIdx.x];
    __syncthreads();
    float acc = bs[d];
    #pragma unroll 8
    for (int n = 0; n < SDIMW; n++)
        acc = fmaf(sf[n], Ws[(size_t)n * DIMW + d], acc);
    cs[(size_t)b * DIMW + d] = acc;
}

__global__ __launch_bounds__(256)
void final_kernel(const float* __restrict__ hid, const float* __restrict__ cs,
                  const float* __restrict__ gamma, const float* __restrict__ beta,
                  float* __restrict__ out)
{
    const int b = blockIdx.x;
    const int tid = threadIdx.x;

    float pooled[4];
    float lsum = 0.f, lsq = 0.f;
    #pragma unroll
    for (int i = 0; i < 4; i++) {
        const int d = i * 256 + tid;
        float acc = 0.f;
        #pragma unroll 8
        for (int s = 0; s < SEQ; s++)
            acc += hid[((size_t)b * SEQ + s) * DIMW + d];
        float p = cs[(size_t)b * DIMW + d] + acc * (1.f / (float)SEQ);
        pooled[i] = p;
        lsum += p;
        lsq  += p * p;
    }

    __shared__ float s1[8], s2[8];
    #pragma unroll
    for (int o = 16; o > 0; o >>= 1) {
        lsum += __shfl_xor_sync(0xffffffffu, lsum, o);
        lsq  += __shfl_xor_sync(0xffffffffu, lsq,  o);
    }
    if ((tid & 31) == 0) { s1[tid >> 5] = lsum; s2[tid >> 5] = lsq; }
    __syncthreads();
    float tsum = 0.f, tsq = 0.f;
    #pragma unroll
    for (int w = 0; w < 8; w++) { tsum += s1[w]; tsq += s2[w]; }

    const float mu  = tsum * (1.f / (float)DIMW);
    const float var = tsq * (1.f / (float)DIMW) - mu * mu;
    const float rstd = rsqrtf(var + EPS);

    #pragma unroll
    for (int i = 0; i < 4; i++) {
        const int d = i * 256 + tid;
        out[(size_t)b * DIMW + d] = (pooled[i] - mu) * rstd * gamma[d] + beta[d];
    }
}

// ---------------------------------------------------------------------------
extern "C" void kernel_launch(void* const* d_in, const int* in_sizes, int n_in,
                              void* d_out, int out_size)
{
    const float* X     = (const float*)d_in[0];
    const float* Wd    = (const float*)d_in[1];
    const float* bd    = (const float*)d_in[2];
    const float* Wi    = (const float*)d_in[3];
    const float* bi    = (const float*)d_in[4];
    const float* A_log = (const float*)d_in[5];
    const float* Wo    = (const float*)d_in[6];
    const float* bo    = (const float*)d_in[7];
    const float* Ws    = (const float*)d_in[8];
    const float* bs    = (const float*)d_in[9];
    const float* gamma = (const float*)d_in[10];
    const float* beta  = (const float*)d_in[11];

    float* out_repr   = (float*)d_out;                         // [B, D]
    float* out_hidden = (float*)d_out + (size_t)BATCH * DIMW;  // [B, S, D]

    float *p_decay, *p_drive, *p_hs, *p_hidden, *p_final, *p_cstate, *p_wt;
    cudaGetSymbolAddress((void**)&p_decay,  g_decay);
    cudaGetSymbolAddress((void**)&p_drive,  g_drive);
    cudaGetSymbolAddress((void**)&p_hs,     g_hs);
    cudaGetSymbolAddress((void**)&p_hidden, g_hidden);
    cudaGetSymbolAddress((void**)&p_final,  g_final);
    cudaGetSymbolAddress((void**)&p_cstate, g_cstate);
    cudaGetSymbolAddress((void**)&p_wt,     g_wt);

    cudaFuncSetAttribute(proj_mma_kernel,
                         cudaFuncAttributeMaxDynamicSharedMemorySize, PJ_SMEM);
    cudaFuncSetAttribute(outgemm_mma_kernel,
                         cudaFuncAttributeMaxDynamicSharedMemorySize, OG_SMEM);

    const size_t WSZ = (size_t)SDIMW * DIMW;
    float* WdT0 = p_wt + 0 * WSZ;
    float* WiT0 = p_wt + 1 * WSZ;
    float* WoT0 = p_wt + 2 * WSZ;
    float* WdT1 = p_wt + 3 * WSZ;
    float* WiT1 = p_wt + 4 * WSZ;
    float* WoT1 = p_wt + 5 * WSZ;

    // transposes (+ tf32 rounding): Wd/Wi [1024,256]->[256,1024]; Wo [256,1024]->[1024,256]
    const dim3 tb(32, 8);
    transpose_kernel<<<dim3(SDIMW / 32, DIMW / 32), tb>>>(Wd,       WdT0, DIMW, SDIMW);
    transpose_kernel<<<dim3(SDIMW / 32, DIMW / 32), tb>>>(Wi,       WiT0, DIMW, SDIMW);
    transpose_kernel<<<dim3(DIMW / 32, SDIMW / 32), tb>>>(Wo,       WoT0, SDIMW, DIMW);
    transpose_kernel<<<dim3(SDIMW / 32, DIMW / 32), tb>>>(Wd + WSZ, WdT1, DIMW, SDIMW);
    transpose_kernel<<<dim3(SDIMW / 32, DIMW / 32), tb>>>(Wi + WSZ, WiT1, DIMW, SDIMW);
    transpose_kernel<<<dim3(DIMW / 32, SDIMW / 32), tb>>>(Wo + WSZ, WoT1, SDIMW, DIMW);

    const dim3 pjGrid(SDIMW / 64, MROWS / 128);    // (4, 128)
    const dim3 ogGrid(DIMW / 128, MROWS / 128);    // (8, 128)
    const dim3 csGrid(DIMW / 256, BATCH);          // (4, 256)

    // ---------------- layer 0 ----------------
    proj_mma_kernel<<<pjGrid, 256, PJ_SMEM>>>(X, WdT0, WiT0, bd, bi, A_log,
                                              p_decay, p_drive);
    scan_kernel<<<BATCH, 256>>>(p_decay, p_drive, p_hs, p_final);
    cstate_kernel<<<csGrid, 256>>>(p_final, Ws, bs, p_cstate);
    outgemm_mma_kernel<<<ogGrid, 256, OG_SMEM>>>(p_hs, WoT0, bo, p_cstate, p_hidden);

    // ---------------- layer 1 ----------------
    proj_mma_kernel<<<pjGrid, 256, PJ_SMEM>>>(p_hidden, WdT1, WiT1, bd + SDIMW,
                                              bi + SDIMW, A_log + SDIMW,
                                              p_decay, p_drive);
    scan_kernel<<<BATCH, 256>>>(p_decay, p_drive, p_hs, p_final);
    cstate_kernel<<<csGrid, 256>>>(p_final, Ws + WSZ, bs + DIMW, p_cstate);
    outgemm_mma_kernel<<<ogGrid, 256, OG_SMEM>>>(p_hs, WoT1, bo + DIMW, p_cstate,
                                                 out_hidden);

    // ---------------- pooling + LayerNorm ----------------
    final_kernel<<<BATCH, 256>>>(out_hidden, p_cstate, gamma, beta, out_repr);
}